// round 2
// baseline (speedup 1.0000x reference)
#include <cuda_runtime.h>
#include <math.h>

// ---------------------------------------------------------------------------
// LSForward: Born-series scattering, M=4096 pts, 4 wavenumbers (0.5*m), 5 iters.
// Matrix-free fused matvec. R1 -> R2: pack row-pairs into f32x2 (FFMA2) to
// halve fma-pipe issue slots (3-reg FFMA is rt=2/SMSP on B300; FFMA2 does 2x
// work per slot). A-vector duplicates prepacked in shared so the complex MAC
// needs zero repacking in the hot loop.
// ---------------------------------------------------------------------------

constexpr int M_PTS  = 4096;
constexpr int NDOBS  = 64;
constexpr int NK     = 4;
constexpr int N_ITER = 5;

constexpr int TPB    = 256;                    // threads per block
constexpr int RPT    = 4;                      // rows per thread (2 packed pairs)
constexpr int NPAIR  = RPT / 2;
constexpr int ROWBLK = M_PTS / (TPB * RPT);    // 4 row-blocks
constexpr int JSPLIT = 128;                    // j-partition count (grid.y)
constexpr int JCHUNK = M_PTS / JSPLIT;         // 32 j's per block

constexpr float C_G = 0.07957747154594767f;    // 1/(4*pi)

typedef unsigned long long u64;

// ---- f32x2 packed helpers (sm_103a FFMA2 path) ----------------------------
__device__ __forceinline__ u64 pk2(float lo, float hi) {
    u64 r; asm("mov.b64 %0,{%1,%2};" : "=l"(r) : "f"(lo), "f"(hi)); return r;
}
__device__ __forceinline__ void upk2(u64 v, float& lo, float& hi) {
    asm("mov.b64 {%0,%1},%2;" : "=f"(lo), "=f"(hi) : "l"(v));
}
__device__ __forceinline__ u64 fma2(u64 a, u64 b, u64 c) {
    u64 d; asm("fma.rn.f32x2 %0,%1,%2,%3;" : "=l"(d) : "l"(a), "l"(b), "l"(c)); return d;
}
__device__ __forceinline__ u64 mul2(u64 a, u64 b) {
    u64 d; asm("mul.rn.f32x2 %0,%1,%2;" : "=l"(d) : "l"(a), "l"(b)); return d;
}
__device__ __forceinline__ u64 add2(u64 a, u64 b) {
    u64 d; asm("add.rn.f32x2 %0,%1,%2;" : "=l"(d) : "l"(a), "l"(b)); return d;
}
__device__ __forceinline__ u64 neg2(u64 a) {           // sign-flip both lanes (alu pipe)
    u64 d; asm("xor.b64 %0,%1,%2;" : "=l"(d) : "l"(a), "l"(0x8000000080000000ULL)); return d;
}
__device__ __forceinline__ u64 f4lo(float4 v) {
    u64 r; asm("mov.b64 %0,{%1,%2};" : "=l"(r) : "f"(v.x), "f"(v.y)); return r;
}
__device__ __forceinline__ u64 f4hi(float4 v) {
    u64 r; asm("mov.b64 %0,{%1,%2};" : "=l"(r) : "f"(v.z), "f"(v.w)); return r;
}

// Scratch (allocation-free: __device__ globals)
__device__ float g_px[M_PTS], g_py[M_PTS], g_pz[M_PTS];
__device__ float g_r2[M_PTS], g_vw[M_PTS];
__device__ float g_p0[NK * 2 * M_PTS];
__device__ float g_p [NK * 2 * M_PTS];
__device__ float g_a [NK * 2 * M_PTS];             // VW * p (matvec input)
__device__ float g_part[JSPLIT][NK * 2 * M_PTS];   // deterministic j-partials (16 MB)

// ---------------------------------------------------------------------------
__global__ void k_init(const float* __restrict__ V,
                       const float* __restrict__ pts,
                       const float* __restrict__ w) {
    int i = blockIdx.x * blockDim.x + threadIdx.x;
    if (i >= M_PTS) return;
    float x = pts[3 * i], y = pts[3 * i + 1], z = pts[3 * i + 2];
    g_px[i] = x; g_py[i] = y; g_pz[i] = z;
    g_r2[i] = x * x + y * y + z * z;
    float vw = V[i] * w[i];
    g_vw[i] = vw;
#pragma unroll
    for (int m = 0; m < NK; m++) {
        float kv = 0.5f * (float)(m + 1);
        float s, c;
        sincosf(kv * z, &s, &c);                 // accurate; cheap kernel
        g_p0[m * 2 * M_PTS + i]          = c;
        g_p0[m * 2 * M_PTS + M_PTS + i]  = s;
        g_p [m * 2 * M_PTS + i]          = c;
        g_p [m * 2 * M_PTS + M_PTS + i]  = s;
        g_a [m * 2 * M_PTS + i]          = vw * c;
        g_a [m * 2 * M_PTS + M_PTS + i]  = vw * s;
    }
}

// ---------------------------------------------------------------------------
// Core Born matvec. Per j, shared holds prepacked duplicates:
//  slot 0: pxd  1: pyd  2: pzd  3: r2d
//  slot 4+3m: Ard(m)  5+3m: Aid(m)  6+3m: nAid(m)   (m = 0..3)
// ---------------------------------------------------------------------------
__global__ __launch_bounds__(TPB) void k_acc() {
    __shared__ alignas(16) u64 sj[JCHUNK][16];

    int t  = threadIdx.x;
    int j0 = blockIdx.y * JCHUNK;

    if (t < JCHUNK) {
        int j = j0 + t;
        float px = g_px[j], py = g_py[j], pz = g_pz[j], r2 = g_r2[j];
        sj[t][0] = pk2(px, px);
        sj[t][1] = pk2(py, py);
        sj[t][2] = pk2(pz, pz);
        sj[t][3] = pk2(r2, r2);
#pragma unroll
        for (int m = 0; m < NK; m++) {
            float ar = g_a[m * 2 * M_PTS + j];
            float ai = g_a[m * 2 * M_PTS + M_PTS + j];
            sj[t][4 + 3 * m] = pk2(ar, ar);
            sj[t][5 + 3 * m] = pk2(ai, ai);
            sj[t][6 + 3 * m] = pk2(-ai, -ai);
        }
    }
    __syncthreads();

    int rbase = blockIdx.x * (TPB * RPT) + t;
    int rows[RPT];
    u64 pxp[NPAIR], pyp[NPAIR], pzp[NPAIR], r2p[NPAIR];
#pragma unroll
    for (int p = 0; p < NPAIR; p++) {
        int ra = rbase + (2 * p) * TPB;
        int rb = rbase + (2 * p + 1) * TPB;
        rows[2 * p] = ra; rows[2 * p + 1] = rb;
        pxp[p] = pk2(g_px[ra], g_px[rb]);
        pyp[p] = pk2(g_py[ra], g_py[rb]);
        pzp[p] = pk2(g_pz[ra], g_pz[rb]);
        r2p[p] = pk2(g_r2[ra], g_r2[rb]);
    }

    u64 accr[NPAIR][NK], acci[NPAIR][NK];
#pragma unroll
    for (int p = 0; p < NPAIR; p++)
#pragma unroll
        for (int m = 0; m < NK; m++) { accr[p][m] = 0ULL; acci[p][m] = 0ULL; }

    const u64 n2d = pk2(-2.f, -2.f);

#pragma unroll 1
    for (int jj = 0; jj < JCHUNK; jj++) {
        const float4* sb = reinterpret_cast<const float4*>(&sj[jj][0]);
        float4 q0 = sb[0], q1 = sb[1], q2 = sb[2], q3 = sb[3];
        float4 q4 = sb[4], q5 = sb[5], q6 = sb[6], q7 = sb[7];
        u64 Pxd = f4lo(q0), Pyd = f4hi(q0), Pzd = f4lo(q1), R2d = f4hi(q1);
        u64 Ard[NK], Aid[NK], nAid[NK];
        Ard[0] = f4lo(q2); Aid[0] = f4hi(q2); nAid[0] = f4lo(q3);
        Ard[1] = f4hi(q3); Aid[1] = f4lo(q4); nAid[1] = f4hi(q4);
        Ard[2] = f4lo(q5); Aid[2] = f4hi(q5); nAid[2] = f4lo(q6);
        Ard[3] = f4hi(q6); Aid[3] = f4lo(q7); nAid[3] = f4hi(q7);
        int jg = j0 + jj;

#pragma unroll
        for (int p = 0; p < NPAIR; p++) {
            // packed geometry for 2 rows
            u64 dot = fma2(pxp[p], Pxd, fma2(pyp[p], Pyd, mul2(pzp[p], Pzd)));
            u64 d2v = fma2(n2d, dot, add2(r2p[p], R2d));
            float d2a, d2b; upk2(d2v, d2a, d2b);
            d2a = fmaxf(d2a, 1e-12f);
            d2b = fmaxf(d2b, 1e-12f);
            float ria = rsqrtf(d2a), rib = rsqrtf(d2b);
            float tha = (0.5f * d2a) * ria;          // theta = 0.5*D
            float thb = (0.5f * d2b) * rib;
            float sca = (rows[2 * p]     == jg) ? 0.f : C_G * ria;
            float scb = (rows[2 * p + 1] == jg) ? 0.f : C_G * rib;
            float sa, ca, sb2, cb;
            __sincosf(tha, &sa, &ca);
            __sincosf(thb, &sb2, &cb);

            u64 cp  = pk2(ca, cb);
            u64 sp  = pk2(sa, sb2);
            u64 scp = pk2(sca, scb);
            u64 tcp = add2(cp, cp);

            // Chebyshev: G_m = sc * exp(i m theta); packed over the 2 rows
            u64 g1r = mul2(scp, cp), g1i = mul2(scp, sp);
            u64 g2r = fma2(tcp, g1r, neg2(scp));
            u64 g2i = mul2(tcp, g1i);
            u64 g3r = fma2(tcp, g2r, neg2(g1r));
            u64 g3i = fma2(tcp, g2i, neg2(g1i));
            u64 g4r = fma2(tcp, g3r, neg2(g2r));
            u64 g4i = fma2(tcp, g3i, neg2(g2i));

            // complex MAC, all operands prepacked:
            // accr += gr*Ar - gi*Ai ; acci += gr*Ai + gi*Ar
            accr[p][0] = fma2(g1r, Ard[0], fma2(g1i, nAid[0], accr[p][0]));
            acci[p][0] = fma2(g1r, Aid[0], fma2(g1i,  Ard[0], acci[p][0]));
            accr[p][1] = fma2(g2r, Ard[1], fma2(g2i, nAid[1], accr[p][1]));
            acci[p][1] = fma2(g2r, Aid[1], fma2(g2i,  Ard[1], acci[p][1]));
            accr[p][2] = fma2(g3r, Ard[2], fma2(g3i, nAid[2], accr[p][2]));
            acci[p][2] = fma2(g3r, Aid[2], fma2(g3i,  Ard[2], acci[p][2]));
            accr[p][3] = fma2(g4r, Ard[3], fma2(g4i, nAid[3], accr[p][3]));
            acci[p][3] = fma2(g4r, Aid[3], fma2(g4i,  Ard[3], acci[p][3]));
        }
    }

    float* part = g_part[blockIdx.y];
#pragma unroll
    for (int p = 0; p < NPAIR; p++) {
        int ra = rows[2 * p], rb = rows[2 * p + 1];
#pragma unroll
        for (int m = 0; m < NK; m++) {
            float xr, yr, xi, yi;
            upk2(accr[p][m], xr, yr);
            upk2(acci[p][m], xi, yi);
            part[m * 2 * M_PTS + ra]         = xr;
            part[m * 2 * M_PTS + rb]         = yr;
            part[m * 2 * M_PTS + M_PTS + ra] = xi;
            part[m * 2 * M_PTS + M_PTS + rb] = yi;
        }
    }
}

// ---------------------------------------------------------------------------
// Deterministic partial reduction + Born update: p = p0 + sum; a = VW*p.
// ---------------------------------------------------------------------------
__global__ void k_update() {
    int e = blockIdx.x * blockDim.x + threadIdx.x;  // 0 .. NK*2*M-1
    float s = 0.f;
#pragma unroll 8
    for (int js = 0; js < JSPLIT; js++) s += g_part[js][e];
    float pv = g_p0[e] + s;
    g_p[e] = pv;
    g_a[e] = g_vw[e & (M_PTS - 1)] * pv;
}

// ---------------------------------------------------------------------------
// Far-field: one block per observation direction.
// ---------------------------------------------------------------------------
__global__ __launch_bounds__(TPB) void k_far(const float* __restrict__ V,
                                             const float* __restrict__ obs,
                                             const float* __restrict__ w,
                                             float* __restrict__ out) {
    int d = blockIdx.x;
    int t = threadIdx.x;
    float ox = obs[3 * d], oy = obs[3 * d + 1], oz = obs[3 * d + 2];

    float fr[NK] = {0.f, 0.f, 0.f, 0.f};
    float fi[NK] = {0.f, 0.f, 0.f, 0.f};

    for (int j = t; j < M_PTS; j += TPB) {
        float q = fmaf(g_px[j], ox, fmaf(g_py[j], oy, g_pz[j] * oz));
        float s1, c1;
        __sincosf(0.5f * q, &s1, &c1);
        float tc = c1 + c1;
        float cm[NK], sm[NK];
        cm[0] = c1;                      sm[0] = s1;
        cm[1] = fmaf(tc, c1, -1.f);      sm[1] = tc * s1;
        cm[2] = fmaf(tc, cm[1], -cm[0]); sm[2] = fmaf(tc, sm[1], -sm[0]);
        cm[3] = fmaf(tc, cm[2], -cm[1]); sm[3] = fmaf(tc, sm[2], -sm[1]);
        float v = V[j], wj = w[j];
#pragma unroll
        for (int m = 0; m < NK; m++) {
            float pr = g_p[m * 2 * M_PTS + j];
            float pi = g_p[m * 2 * M_PTS + M_PTS + j];
            float zr = v * pr, zi = v * pi;
            float ir = fmaf(zr, cm[m],  zi * sm[m]);   // exp(-ikQ)
            float ii = fmaf(zi, cm[m], -zr * sm[m]);
            fr[m] = fmaf(wj, ir, fr[m]);
            fi[m] = fmaf(wj, ii, fi[m]);
        }
    }

#pragma unroll
    for (int off = 16; off; off >>= 1) {
#pragma unroll
        for (int m = 0; m < NK; m++) {
            fr[m] += __shfl_down_sync(0xffffffffu, fr[m], off);
            fi[m] += __shfl_down_sync(0xffffffffu, fi[m], off);
        }
    }
    __shared__ float sred[8][TPB / 32];
    int lane = t & 31, wid = t >> 5;
    if (lane == 0) {
#pragma unroll
        for (int m = 0; m < NK; m++) {
            sred[2 * m][wid]     = fr[m];
            sred[2 * m + 1][wid] = fi[m];
        }
    }
    __syncthreads();
    if (t < 8) {
        float s = 0.f;
#pragma unroll
        for (int wdx = 0; wdx < TPB / 32; wdx++) s += sred[t][wdx];
        int m = t >> 1, c = t & 1;
        out[m * NDOBS * 2 + d * 2 + c] = -C_G * s;
    }
}

// ---------------------------------------------------------------------------
extern "C" void kernel_launch(void* const* d_in, const int* in_sizes, int n_in,
                              void* d_out, int out_size) {
    const float* V   = (const float*)d_in[0];   // [4096]
    const float* obs = (const float*)d_in[1];   // [64,3]
    const float* pts = (const float*)d_in[2];   // [4096,3]
    const float* w   = (const float*)d_in[3];   // [4096]
    float* out = (float*)d_out;                 // [4,64,2]

    k_init<<<M_PTS / TPB, TPB>>>(V, pts, w);
    for (int it = 0; it < N_ITER; it++) {
        k_acc<<<dim3(ROWBLK, JSPLIT), TPB>>>();
        k_update<<<(NK * 2 * M_PTS) / TPB, TPB>>>();
    }
    k_far<<<NDOBS, TPB>>>(V, obs, w, out);
}

// round 3
// speedup vs baseline: 1.3139x; 1.3139x over previous
#include <cuda_runtime.h>
#include <math.h>

// ---------------------------------------------------------------------------
// LSForward: Born-series scattering, M=4096 pts, 4 wavenumbers (0.5*m), 5 iters.
// Matrix-free fused matvec, scalar FFMA form (FFMA2 proved rt=4 on sm_103a: no
// gain). R3: (a) op-trim via e=0.25*d2 -> theta=sqrt.approx(e), sc=rsqrt(e),
// 0.5*C_G folded into the a-vector; (b) occupancy fix: 1024 blocks of 128 thr
// (R1 had only 256 blocks -> 20% occ; fma pipe was ~82% of its 3-reg ceiling
// with 18% latency exposure).
// ---------------------------------------------------------------------------

constexpr int M_PTS  = 4096;
constexpr int NDOBS  = 64;
constexpr int NK     = 4;
constexpr int N_ITER = 5;

constexpr int TPB    = 128;                    // threads per block
constexpr int RPT    = 2;                      // rows per thread
constexpr int ROWBLK = M_PTS / (TPB * RPT);    // 16 row-blocks
constexpr int JSPLIT = 64;                     // j-partition count (grid.y)
constexpr int JCHUNK = M_PTS / JSPLIT;         // 64 j's per block

constexpr float C_G = 0.07957747154594767f;    // 1/(4*pi)

// Scratch (allocation-free: __device__ globals)
__device__ float g_px[M_PTS], g_py[M_PTS], g_pz[M_PTS];
__device__ float g_r2q[M_PTS];                     // 0.25 * |p|^2
__device__ float g_vw[M_PTS];                      // 0.5*C_G * V * w  (folded scale)
__device__ float g_p0[NK * 2 * M_PTS];
__device__ float g_p [NK * 2 * M_PTS];
__device__ float g_a [NK * 2 * M_PTS];             // folded matvec input
__device__ float g_part[JSPLIT][NK * 2 * M_PTS];   // deterministic j-partials (8 MB)

__device__ __forceinline__ float fsqrt_approx(float x) {
    float r; asm("sqrt.approx.f32 %0,%1;" : "=f"(r) : "f"(x)); return r;
}

// ---------------------------------------------------------------------------
__global__ void k_init(const float* __restrict__ V,
                       const float* __restrict__ pts,
                       const float* __restrict__ w) {
    int i = blockIdx.x * blockDim.x + threadIdx.x;
    if (i >= M_PTS) return;
    float x = pts[3 * i], y = pts[3 * i + 1], z = pts[3 * i + 2];
    g_px[i] = x; g_py[i] = y; g_pz[i] = z;
    g_r2q[i] = 0.25f * (x * x + y * y + z * z);
    float vw = 0.5f * C_G * V[i] * w[i];           // fold 0.5*C_G into a
    g_vw[i] = vw;
#pragma unroll
    for (int m = 0; m < NK; m++) {
        float kv = 0.5f * (float)(m + 1);
        float s, c;
        sincosf(kv * z, &s, &c);                   // accurate; cheap kernel
        g_p0[m * 2 * M_PTS + i]          = c;
        g_p0[m * 2 * M_PTS + M_PTS + i]  = s;
        g_p [m * 2 * M_PTS + i]          = c;
        g_p [m * 2 * M_PTS + M_PTS + i]  = s;
        g_a [m * 2 * M_PTS + i]          = vw * c;
        g_a [m * 2 * M_PTS + M_PTS + i]  = vw * s;
    }
}

// ---------------------------------------------------------------------------
// Core Born matvec: grid (ROWBLK, JSPLIT), 256 rows x 64 j per block.
// Per pair: e = 0.25*d2 ; theta = sqrt(e) (= 0.5*D) ; sc = rsqrt(e) (= 2/D,
// with 0.5*C_G prefolded into a). Chebyshev G_m = sc * exp(i*m*theta).
// ---------------------------------------------------------------------------
__global__ __launch_bounds__(TPB) void k_acc() {
    __shared__ alignas(16) float sj[JCHUNK][12];  // px,py,pz,r2q, ar0,ai0..ar3,ai3

    int t  = threadIdx.x;
    int j0 = blockIdx.y * JCHUNK;

    if (t < JCHUNK) {
        int j = j0 + t;
        sj[t][0] = g_px[j];
        sj[t][1] = g_py[j];
        sj[t][2] = g_pz[j];
        sj[t][3] = g_r2q[j];
#pragma unroll
        for (int m = 0; m < NK; m++) {
            sj[t][4 + 2 * m] = g_a[m * 2 * M_PTS + j];
            sj[t][5 + 2 * m] = g_a[m * 2 * M_PTS + M_PTS + j];
        }
    }
    __syncthreads();

    int rbase = blockIdx.x * (TPB * RPT) + t;
    float pix[RPT], piy[RPT], piz[RPT], r2i[RPT];
#pragma unroll
    for (int r = 0; r < RPT; r++) {
        int row = rbase + r * TPB;
        pix[r] = g_px[row]; piy[r] = g_py[row];
        piz[r] = g_pz[row]; r2i[r] = g_r2q[row];
    }

    float accr[RPT][NK], acci[RPT][NK];
#pragma unroll
    for (int r = 0; r < RPT; r++)
#pragma unroll
        for (int m = 0; m < NK; m++) { accr[r][m] = 0.f; acci[r][m] = 0.f; }

#pragma unroll 2
    for (int jj = 0; jj < JCHUNK; jj++) {
        float4 P  = *reinterpret_cast<const float4*>(&sj[jj][0]);
        float4 A0 = *reinterpret_cast<const float4*>(&sj[jj][4]);
        float4 A1 = *reinterpret_cast<const float4*>(&sj[jj][8]);
        int jg = j0 + jj;
#pragma unroll
        for (int r = 0; r < RPT; r++) {
            int row = rbase + r * TPB;
            float dot = fmaf(pix[r], P.x, fmaf(piy[r], P.y, piz[r] * P.z));
            float e   = fmaf(-0.5f, dot, r2i[r] + P.w);     // 0.25 * d2
            e = fmaxf(e, 2.5e-13f);
            float th  = fsqrt_approx(e);                    // 0.5 * D
            float sc  = rsqrtf(e);                          // 2/D (scale prefolded)
            sc = (row == jg) ? 0.f : sc;
            float s1, c1;
            __sincosf(th, &s1, &c1);
            float tc  = c1 + c1;
            // Chebyshev: G_m = sc * exp(i m theta)
            float g1r = sc * c1,             g1i = sc * s1;
            float g2r = fmaf(tc, g1r, -sc);  float g2i = tc * g1i;
            float g3r = fmaf(tc, g2r, -g1r); float g3i = fmaf(tc, g2i, -g1i);
            float g4r = fmaf(tc, g3r, -g2r); float g4i = fmaf(tc, g3i, -g2i);
            // complex MAC (negations free in FFMA modifiers)
            accr[r][0] = fmaf(g1r, A0.x, fmaf(-g1i, A0.y, accr[r][0]));
            acci[r][0] = fmaf(g1r, A0.y, fmaf( g1i, A0.x, acci[r][0]));
            accr[r][1] = fmaf(g2r, A0.z, fmaf(-g2i, A0.w, accr[r][1]));
            acci[r][1] = fmaf(g2r, A0.w, fmaf( g2i, A0.z, acci[r][1]));
            accr[r][2] = fmaf(g3r, A1.x, fmaf(-g3i, A1.y, accr[r][2]));
            acci[r][2] = fmaf(g3r, A1.y, fmaf( g3i, A1.x, acci[r][2]));
            accr[r][3] = fmaf(g4r, A1.z, fmaf(-g4i, A1.w, accr[r][3]));
            acci[r][3] = fmaf(g4r, A1.w, fmaf( g4i, A1.z, acci[r][3]));
        }
    }

    float* part = g_part[blockIdx.y];
#pragma unroll
    for (int r = 0; r < RPT; r++) {
        int row = rbase + r * TPB;
#pragma unroll
        for (int m = 0; m < NK; m++) {
            part[m * 2 * M_PTS + row]         = accr[r][m];
            part[m * 2 * M_PTS + M_PTS + row] = acci[r][m];
        }
    }
}

// ---------------------------------------------------------------------------
// Deterministic partial reduction + Born update: p = p0 + sum; a = vw*p.
// ---------------------------------------------------------------------------
__global__ void k_update() {
    int e = blockIdx.x * blockDim.x + threadIdx.x;  // 0 .. NK*2*M-1
    float s = 0.f;
#pragma unroll 8
    for (int js = 0; js < JSPLIT; js++) s += g_part[js][e];
    float pv = g_p0[e] + s;
    g_p[e] = pv;
    g_a[e] = g_vw[e & (M_PTS - 1)] * pv;            // vw already 0.5*C_G*V*w
}

// ---------------------------------------------------------------------------
// Far-field: one block per observation direction.
// ---------------------------------------------------------------------------
__global__ __launch_bounds__(256) void k_far(const float* __restrict__ V,
                                             const float* __restrict__ obs,
                                             const float* __restrict__ w,
                                             float* __restrict__ out) {
    constexpr int FTPB = 256;
    int d = blockIdx.x;
    int t = threadIdx.x;
    float ox = obs[3 * d], oy = obs[3 * d + 1], oz = obs[3 * d + 2];

    float fr[NK] = {0.f, 0.f, 0.f, 0.f};
    float fi[NK] = {0.f, 0.f, 0.f, 0.f};

    for (int j = t; j < M_PTS; j += FTPB) {
        float q = fmaf(g_px[j], ox, fmaf(g_py[j], oy, g_pz[j] * oz));
        float s1, c1;
        __sincosf(0.5f * q, &s1, &c1);
        float tc = c1 + c1;
        float cm[NK], sm[NK];
        cm[0] = c1;                      sm[0] = s1;
        cm[1] = fmaf(tc, c1, -1.f);      sm[1] = tc * s1;
        cm[2] = fmaf(tc, cm[1], -cm[0]); sm[2] = fmaf(tc, sm[1], -sm[0]);
        cm[3] = fmaf(tc, cm[2], -cm[1]); sm[3] = fmaf(tc, sm[2], -sm[1]);
        float v = V[j], wj = w[j];
#pragma unroll
        for (int m = 0; m < NK; m++) {
            float pr = g_p[m * 2 * M_PTS + j];
            float pi = g_p[m * 2 * M_PTS + M_PTS + j];
            float zr = v * pr, zi = v * pi;
            float ir = fmaf(zr, cm[m],  zi * sm[m]);   // exp(-ikQ)
            float ii = fmaf(zi, cm[m], -zr * sm[m]);
            fr[m] = fmaf(wj, ir, fr[m]);
            fi[m] = fmaf(wj, ii, fi[m]);
        }
    }

#pragma unroll
    for (int off = 16; off; off >>= 1) {
#pragma unroll
        for (int m = 0; m < NK; m++) {
            fr[m] += __shfl_down_sync(0xffffffffu, fr[m], off);
            fi[m] += __shfl_down_sync(0xffffffffu, fi[m], off);
        }
    }
    __shared__ float sred[8][FTPB / 32];
    int lane = t & 31, wid = t >> 5;
    if (lane == 0) {
#pragma unroll
        for (int m = 0; m < NK; m++) {
            sred[2 * m][wid]     = fr[m];
            sred[2 * m + 1][wid] = fi[m];
        }
    }
    __syncthreads();
    if (t < 8) {
        float s = 0.f;
#pragma unroll
        for (int wdx = 0; wdx < FTPB / 32; wdx++) s += sred[t][wdx];
        int m = t >> 1, c = t & 1;
        out[m * NDOBS * 2 + d * 2 + c] = -C_G * s;
    }
}

// ---------------------------------------------------------------------------
extern "C" void kernel_launch(void* const* d_in, const int* in_sizes, int n_in,
                              void* d_out, int out_size) {
    const float* V   = (const float*)d_in[0];   // [4096]
    const float* obs = (const float*)d_in[1];   // [64,3]
    const float* pts = (const float*)d_in[2];   // [4096,3]
    const float* w   = (const float*)d_in[3];   // [4096]
    float* out = (float*)d_out;                 // [4,64,2]

    k_init<<<M_PTS / 256, 256>>>(V, pts, w);
    for (int it = 0; it < N_ITER; it++) {
        k_acc<<<dim3(ROWBLK, JSPLIT), TPB>>>();
        k_update<<<(NK * 2 * M_PTS) / 256, 256>>>();
    }
    k_far<<<NDOBS, 256>>>(V, obs, w, out);
}